// round 7
// baseline (speedup 1.0000x reference)
#include <cuda_runtime.h>
#include <math.h>
#include <stdint.h>

// Problem constants
#define B_  4
#define T_  1024
#define D_  2048
#define KV_ 512
#define NH_ 32
#define NKV_ 8
#define HD_ 64
#define MROWS (B_*T_)   // 4096

// Scratch (static device globals; no runtime allocation)
__device__ float g_Q[MROWS * D_];      // rope'd, pre-scaled by 1/8, tf32-rounded
__device__ float g_KV[MROWS * 1024];   // per row: [k(512) | v(512)], tf32-rounded
__device__ float g_KN[B_ * NKV_ * T_]; // 0.5*||k||^2 / 8 per key
__device__ float g_Y[MROWS * D_];      // attention out, (b,t,h*hd), tf32-rounded
__device__ float g_xr[MROWS * D_];     // tf32-rounded x
// tf32-rounded TRANSPOSED weights ([N][K] K-major) for GEMM B operand
__device__ float g_Wqt[D_ * D_];
__device__ float g_Wkvt[1024 * D_];    // rows 0..511 = Wk^T, 512..1023 = Wv^T
__device__ float g_Wot[D_ * D_];

// ---------------------------------------------------------------------------
// helpers
// ---------------------------------------------------------------------------
__device__ __forceinline__ uint32_t f2tf32(float x) {
    uint32_t r;
    asm("cvt.rna.tf32.f32 %0, %1;" : "=r"(r) : "f"(x));
    return r;
}
__device__ __forceinline__ float tf32r(float x) { return __uint_as_float(f2tf32(x)); }

__device__ __forceinline__ void mma_tf32(float c[4],
    uint32_t a0, uint32_t a1, uint32_t a2, uint32_t a3,
    uint32_t b0, uint32_t b1)
{
    asm volatile(
        "mma.sync.aligned.m16n8k8.row.col.f32.tf32.tf32.f32 "
        "{%0,%1,%2,%3}, {%4,%5,%6,%7}, {%8,%9}, {%0,%1,%2,%3};"
        : "+f"(c[0]), "+f"(c[1]), "+f"(c[2]), "+f"(c[3])
        : "r"(a0), "r"(a1), "r"(a2), "r"(a3), "r"(b0), "r"(b1));
}

__device__ __forceinline__ void cp_async16(uint32_t smem, const void* gmem) {
    asm volatile("cp.async.cg.shared.global [%0], [%1], 16;" :: "r"(smem), "l"(gmem));
}
__device__ __forceinline__ void cp_commit() {
    asm volatile("cp.async.commit_group;");
}
template<int N> __device__ __forceinline__ void cp_wait() {
    asm volatile("cp.async.wait_group %0;" :: "n"(N));
}
__device__ __forceinline__ uint32_t smem_u32(const void* p) {
    return (uint32_t)__cvta_generic_to_shared(p);
}

// ---------------------------------------------------------------------------
// tf32 GEMM v3: C[M,N] = A[M,K] @ Bt[N,K]^T, all K-major, pre-rounded tf32.
// Tile 128x128xBK32, 2-stage cp.async, 256 thr (8 warps 2Mx4N), warp 64x32.
// Dynamic smem: As [2][128][36], Bs [2][128][36] (B tile = 128 N-rows x 32 k).
// Fragment banks: A (4g+t) distinct; B (4g+t) distinct (288%32==0).
// 2 CTAs/SM (73728B dyn smem each).
// ---------------------------------------------------------------------------
#define GM_STRIDE 36
#define GM_TILE_ELEMS (2 * 128 * GM_STRIDE)            // 9216 floats per operand
#define GM_SMEM_BYTES (2 * GM_TILE_ELEMS * 4)          // 73728

__global__ __launch_bounds__(256, 2) void gemm_tf32_v3(
    const float* __restrict__ A, const float* __restrict__ Bt,
    float* __restrict__ C, int N, int K)
{
    extern __shared__ float sm[];
    float* As = sm;                  // [2][128][36]
    float* Bs = sm + GM_TILE_ELEMS;  // [2][128][36]

    const int tid  = threadIdx.x;
    const int lane = tid & 31;
    const int wid  = tid >> 5;
    const int g    = lane >> 2;
    const int t    = lane & 3;
    const int wm   = (wid & 1) * 64;
    const int wn   = (wid >> 1) * 32;
    const int bx = blockIdx.x, by = blockIdx.y;

    float acc[4][4][4];
#pragma unroll
    for (int mi = 0; mi < 4; mi++)
#pragma unroll
        for (int nj = 0; nj < 4; nj++)
#pragma unroll
            for (int e = 0; e < 4; e++) acc[mi][nj][e] = 0.f;

    const float* Ab = A  + (size_t)(by * 128) * K;
    const float* Bb = Bt + (size_t)(bx * 128) * K;

    // both tiles: 128 rows x 32 k-cols, 16 floats per thread
    const int r  = tid >> 1;            // 0..127
    const int c0 = (tid & 1) * 16;      // 0 or 16

    const int niter = K >> 5;

#define TS_IDX(s, rr, cc) ((((s) * 128) + (rr)) * GM_STRIDE + (cc))

    // prologue: tile 0 -> stage 0
#pragma unroll
    for (int u = 0; u < 4; u++)
        cp_async16(smem_u32(&As[TS_IDX(0, r, c0 + 4 * u)]), Ab + (size_t)r * K + c0 + 4 * u);
#pragma unroll
    for (int u = 0; u < 4; u++)
        cp_async16(smem_u32(&Bs[TS_IDX(0, r, c0 + 4 * u)]), Bb + (size_t)r * K + c0 + 4 * u);
    cp_commit();

    for (int it = 0; it < niter; it++) {
        const int cb = it & 1;
        if (it + 1 < niter) {
            const int k0 = (it + 1) << 5;
            const int nb = cb ^ 1;
#pragma unroll
            for (int u = 0; u < 4; u++)
                cp_async16(smem_u32(&As[TS_IDX(nb, r, c0 + 4 * u)]),
                           Ab + (size_t)r * K + k0 + c0 + 4 * u);
#pragma unroll
            for (int u = 0; u < 4; u++)
                cp_async16(smem_u32(&Bs[TS_IDX(nb, r, c0 + 4 * u)]),
                           Bb + (size_t)r * K + k0 + c0 + 4 * u);
            cp_commit();
            cp_wait<1>();
        } else {
            cp_wait<0>();
        }
        __syncthreads();

#pragma unroll
        for (int ks = 0; ks < 4; ks++) {
            const int kc = ks * 8;
            uint32_t a[4][4];
#pragma unroll
            for (int mi = 0; mi < 4; mi++) {
                const int r0 = wm + mi * 16 + g;
                a[mi][0] = __float_as_uint(As[TS_IDX(cb, r0,     kc + t)]);
                a[mi][1] = __float_as_uint(As[TS_IDX(cb, r0 + 8, kc + t)]);
                a[mi][2] = __float_as_uint(As[TS_IDX(cb, r0,     kc + t + 4)]);
                a[mi][3] = __float_as_uint(As[TS_IDX(cb, r0 + 8, kc + t + 4)]);
            }
            uint32_t b[4][2];
#pragma unroll
            for (int nj = 0; nj < 4; nj++) {
                const int n0 = wn + nj * 8 + g;      // B element [n0][k]
                b[nj][0] = __float_as_uint(Bs[TS_IDX(cb, n0, kc + t)]);
                b[nj][1] = __float_as_uint(Bs[TS_IDX(cb, n0, kc + t + 4)]);
            }
#pragma unroll
            for (int mi = 0; mi < 4; mi++)
#pragma unroll
                for (int nj = 0; nj < 4; nj++)
                    mma_tf32(acc[mi][nj], a[mi][0], a[mi][1], a[mi][2], a[mi][3],
                             b[nj][0], b[nj][1]);
        }
        __syncthreads();
    }

#pragma unroll
    for (int mi = 0; mi < 4; mi++) {
        const int r0 = by * 128 + wm + mi * 16 + g;
#pragma unroll
        for (int nj = 0; nj < 4; nj++) {
            const int col = bx * 128 + wn + nj * 8 + 2 * t;
            *(float2*)(C + (size_t)r0 * N + col)       = make_float2(acc[mi][nj][0], acc[mi][nj][1]);
            *(float2*)(C + (size_t)(r0 + 8) * N + col) = make_float2(acc[mi][nj][2], acc[mi][nj][3]);
        }
    }
}

// ---------------------------------------------------------------------------
// Elementwise tf32 rounding pass (float4 per thread)
// ---------------------------------------------------------------------------
__global__ void round4_kernel(const float* __restrict__ s, float* __restrict__ d, int n4)
{
    int i = blockIdx.x * blockDim.x + threadIdx.x;
    if (i < n4) {
        float4 v = ((const float4*)s)[i];
        v.x = tf32r(v.x); v.y = tf32r(v.y); v.z = tf32r(v.z); v.w = tf32r(v.w);
        ((float4*)d)[i] = v;
    }
}

// ---------------------------------------------------------------------------
// Transpose + tf32 round: in[rows][cols] -> out[cols][rows]
// grid (cols/32, rows/32), block (32,8)
// ---------------------------------------------------------------------------
__global__ void transpose_tf32_kernel(const float* __restrict__ in, float* __restrict__ out,
                                      int rows, int cols)
{
    __shared__ float s[32][33];
    const int c0 = blockIdx.x * 32, r0 = blockIdx.y * 32;
    const int tx = threadIdx.x, ty = threadIdx.y;
#pragma unroll
    for (int i = 0; i < 4; i++)
        s[ty + 8 * i][tx] = in[(size_t)(r0 + ty + 8 * i) * cols + c0 + tx];
    __syncthreads();
#pragma unroll
    for (int i = 0; i < 4; i++)
        out[(size_t)(c0 + ty + 8 * i) * rows + r0 + tx] = tf32r(s[tx][ty + 8 * i]);
}

// ---------------------------------------------------------------------------
// RoPE for Q (in place): scale by 0.125, round to tf32.
// grid = MROWS, block = NH*32 = 1024.
// ---------------------------------------------------------------------------
__global__ void rope_q_kernel()
{
    const int row  = blockIdx.x;
    const int tpos = row & (T_ - 1);
    const int h = threadIdx.x >> 5;
    const int i = threadIdx.x & 31;

    float inv = 1.0f / powf(10000.0f, (float)i * (1.0f / 32.0f));
    float s, c;
    sincosf((float)tpos * inv, &s, &c);

    float* p = g_Q + (size_t)row * D_ + h * HD_;
    float x1 = p[i], x2 = p[i + 32];
    p[i]      = tf32r((x1 * c - x2 * s) * 0.125f);
    p[i + 32] = tf32r((x2 * c + x1 * s) * 0.125f);
}

// ---------------------------------------------------------------------------
// RoPE for K (in place in g_KV, rounded) + kn from ROUNDED k + round V half.
// grid = MROWS, block = 256 (8 warps: one per kv head).
// ---------------------------------------------------------------------------
__global__ void rope_k_kernel()
{
    const int row  = blockIdx.x;
    const int tpos = row & (T_ - 1);
    const int h = threadIdx.x >> 5;
    const int i = threadIdx.x & 31;

    float inv = 1.0f / powf(10000.0f, (float)i * (1.0f / 32.0f));
    float s, c;
    sincosf((float)tpos * inv, &s, &c);

    float* p = g_KV + (size_t)row * 1024 + h * HD_;
    float x1 = p[i], x2 = p[i + 32];
    float o1 = tf32r(x1 * c - x2 * s);
    float o2 = tf32r(x2 * c + x1 * s);
    p[i]      = o1;
    p[i + 32] = o2;

    float nsq = o1 * o1 + o2 * o2;
#pragma unroll
    for (int off = 16; off; off >>= 1)
        nsq += __shfl_xor_sync(0xffffffffu, nsq, off);
    if (i == 0) {
        int bb = row / T_;
        g_KN[(bb * NKV_ + h) * T_ + tpos] = nsq * 0.0625f;  // 0.5/8
    }

    // round V half (512 floats at offset 512, 256 threads -> 2 each)
    float* vp = g_KV + (size_t)row * 1024 + 512;
    int j = threadIdx.x;
    vp[j]       = tf32r(vp[j]);
    vp[j + 256] = tf32r(vp[j + 256]);
}

// ---------------------------------------------------------------------------
// Flash attention via tf32 mma.sync. Block = 128 thr (4 warps), 64 q-rows.
// grid = (T/64, B*NH); heavy (long causal window) blocks first.
// K/V read from fused g_KV (row stride 1024, V at +512).
// ---------------------------------------------------------------------------
__global__ __launch_bounds__(128) void flash_mma_kernel()
{
    __shared__ float Ks[64][68];
    __shared__ float Vs[64][72];
    __shared__ float kns[64];

    const int bh  = blockIdx.y;
    const int bb  = bh >> 5;
    const int h   = bh & 31;
    const int kvh = h >> 2;
    const int qb  = gridDim.x - 1 - blockIdx.x;   // heavy first
    const int q0  = qb << 6;
    const int tid = threadIdx.x;
    const int w   = tid >> 5;
    const int lane = tid & 31;
    const int g   = lane >> 2;
    const int t   = lane & 3;

    {
        const int r = tid >> 1, ch = (tid & 1) << 5;
        const float* qp = g_Q + (size_t)(bb * T_ + q0 + r) * D_ + h * HD_ + ch;
#pragma unroll
        for (int u = 0; u < 8; u++)
            *(float4*)&Ks[r][ch + 4 * u] = ((const float4*)qp)[u];
    }
    __syncthreads();

    uint32_t aq[8][4];
    const int qr = w * 16 + g;
#pragma unroll
    for (int ks = 0; ks < 8; ks++) {
        aq[ks][0] = __float_as_uint(Ks[qr][ks * 8 + t]);
        aq[ks][1] = __float_as_uint(Ks[qr + 8][ks * 8 + t]);
        aq[ks][2] = __float_as_uint(Ks[qr][ks * 8 + t + 4]);
        aq[ks][3] = __float_as_uint(Ks[qr + 8][ks * 8 + t + 4]);
    }
    __syncthreads();

    float oa[8][4];
#pragma unroll
    for (int nd = 0; nd < 8; nd++)
#pragma unroll
        for (int e = 0; e < 4; e++) oa[nd][e] = 0.f;
    float m0 = -1e30f, m1 = -1e30f, l0 = 0.f, l1 = 0.f;

    const int ntiles = qb + 1;
    const int lr = tid >> 1, lch = (tid & 1) << 5;

    for (int kt = 0; kt < ntiles; kt++) {
        const int kbase = kt << 6;
        const float* kp = g_KV + (size_t)(bb * T_ + kbase + lr) * 1024 + kvh * HD_ + lch;
        const float* vp = kp + 512;

        __syncthreads();
#pragma unroll
        for (int u = 0; u < 8; u++)
            *(float4*)&Ks[lr][lch + 4 * u] = ((const float4*)kp)[u];
#pragma unroll
        for (int u = 0; u < 8; u++)
            *(float4*)&Vs[lr][lch + 4 * u] = ((const float4*)vp)[u];
        if (tid < 64)
            kns[tid] = g_KN[(bb * NKV_ + kvh) * T_ + kbase + tid];
        __syncthreads();

        float sc[8][4];
#pragma unroll
        for (int nj = 0; nj < 8; nj++)
#pragma unroll
            for (int e = 0; e < 4; e++) sc[nj][e] = 0.f;
#pragma unroll
        for (int ks = 0; ks < 8; ks++) {
#pragma unroll
            for (int nj = 0; nj < 8; nj++) {
                uint32_t b0 = __float_as_uint(Ks[nj * 8 + g][ks * 8 + t]);
                uint32_t b1 = __float_as_uint(Ks[nj * 8 + g][ks * 8 + t + 4]);
                mma_tf32(sc[nj], aq[ks][0], aq[ks][1], aq[ks][2], aq[ks][3], b0, b1);
            }
        }

        float mr0 = -1e30f, mr1 = -1e30f;
        const bool diag = (kt == qb);
#pragma unroll
        for (int nj = 0; nj < 8; nj++) {
            const int c0 = nj * 8 + 2 * t, c1 = c0 + 1;
            float kn0 = kns[c0], kn1 = kns[c1];
            sc[nj][0] -= kn0; sc[nj][1] -= kn1;
            sc[nj][2] -= kn0; sc[nj][3] -= kn1;
            if (diag) {
                const int r0 = w * 16 + g, r1 = r0 + 8;
                if (c0 > r0) sc[nj][0] = -1e30f;
                if (c1 > r0) sc[nj][1] = -1e30f;
                if (c0 > r1) sc[nj][2] = -1e30f;
                if (c1 > r1) sc[nj][3] = -1e30f;
            }
            mr0 = fmaxf(mr0, fmaxf(sc[nj][0], sc[nj][1]));
            mr1 = fmaxf(mr1, fmaxf(sc[nj][2], sc[nj][3]));
        }
        mr0 = fmaxf(mr0, __shfl_xor_sync(0xffffffffu, mr0, 1));
        mr0 = fmaxf(mr0, __shfl_xor_sync(0xffffffffu, mr0, 2));
        mr1 = fmaxf(mr1, __shfl_xor_sync(0xffffffffu, mr1, 1));
        mr1 = fmaxf(mr1, __shfl_xor_sync(0xffffffffu, mr1, 2));

        const float mn0 = fmaxf(m0, mr0), mn1 = fmaxf(m1, mr1);
        const float cor0 = __expf(m0 - mn0), cor1 = __expf(m1 - mn1);
        m0 = mn0; m1 = mn1;

        float ps0 = 0.f, ps1 = 0.f;
#pragma unroll
        for (int nj = 0; nj < 8; nj++) {
            sc[nj][0] = __expf(sc[nj][0] - mn0);
            sc[nj][1] = __expf(sc[nj][1] - mn0);
            sc[nj][2] = __expf(sc[nj][2] - mn1);
            sc[nj][3] = __expf(sc[nj][3] - mn1);
            ps0 += sc[nj][0] + sc[nj][1];
            ps1 += sc[nj][2] + sc[nj][3];
        }
        ps0 += __shfl_xor_sync(0xffffffffu, ps0, 1);
        ps0 += __shfl_xor_sync(0xffffffffu, ps0, 2);
        ps1 += __shfl_xor_sync(0xffffffffu, ps1, 1);
        ps1 += __shfl_xor_sync(0xffffffffu, ps1, 2);
        l0 = l0 * cor0 + ps0;
        l1 = l1 * cor1 + ps1;

#pragma unroll
        for (int nd = 0; nd < 8; nd++) {
            oa[nd][0] *= cor0; oa[nd][1] *= cor0;
            oa[nd][2] *= cor1; oa[nd][3] *= cor1;
        }

        const int s0 = (lane & ~3) | (t >> 1);
        const int s1 = s0 + 2;
        const bool odd = (t & 1);
#pragma unroll
        for (int ks = 0; ks < 8; ks++) {
            float p0 = sc[ks][0], p1 = sc[ks][1], p2 = sc[ks][2], p3 = sc[ks][3];
            float x0 = __shfl_sync(0xffffffffu, p0, s0);
            float x1 = __shfl_sync(0xffffffffu, p1, s0);
            float y0 = __shfl_sync(0xffffffffu, p0, s1);
            float y1 = __shfl_sync(0xffffffffu, p1, s1);
            float z0 = __shfl_sync(0xffffffffu, p2, s0);
            float z1 = __shfl_sync(0xffffffffu, p3, s0);
            float u0 = __shfl_sync(0xffffffffu, p2, s1);
            float u1 = __shfl_sync(0xffffffffu, p3, s1);
            uint32_t a0 = f2tf32(odd ? x1 : x0);
            uint32_t a1 = f2tf32(odd ? z1 : z0);
            uint32_t a2 = f2tf32(odd ? y1 : y0);
            uint32_t a3 = f2tf32(odd ? u1 : u0);
#pragma unroll
            for (int nd = 0; nd < 8; nd++) {
                uint32_t b0 = __float_as_uint(Vs[ks * 8 + t][nd * 8 + g]);
                uint32_t b1 = __float_as_uint(Vs[ks * 8 + t + 4][nd * 8 + g]);
                mma_tf32(oa[nd], a0, a1, a2, a3, b0, b1);
            }
        }
    }

    const float il0 = 1.0f / l0, il1 = 1.0f / l1;
    const int qrow = q0 + w * 16 + g;
    float* yp0 = g_Y + (size_t)(bb * T_ + qrow) * D_ + h * HD_;
    float* yp1 = yp0 + (size_t)8 * D_;
#pragma unroll
    for (int nd = 0; nd < 8; nd++) {
        const int col = nd * 8 + 2 * t;
        *(float2*)(yp0 + col) = make_float2(tf32r(oa[nd][0] * il0), tf32r(oa[nd][1] * il0));
        *(float2*)(yp1 + col) = make_float2(tf32r(oa[nd][2] * il1), tf32r(oa[nd][3] * il1));
    }
}

// ---------------------------------------------------------------------------
extern "C" void kernel_launch(void* const* d_in, const int* in_sizes, int n_in,
                              void* d_out, int out_size)
{
    const float* x  = (const float*)d_in[0];
    const float* Wq = (const float*)d_in[1];
    const float* Wk = (const float*)d_in[2];
    const float* Wv = (const float*)d_in[3];
    const float* Wo = (const float*)d_in[4];
    float* out = (float*)d_out;

    float *Q, *KV, *Y, *xr, *Wqt, *Wkvt, *Wot;
    cudaGetSymbolAddress((void**)&Q, g_Q);
    cudaGetSymbolAddress((void**)&KV, g_KV);
    cudaGetSymbolAddress((void**)&Y, g_Y);
    cudaGetSymbolAddress((void**)&xr, g_xr);
    cudaGetSymbolAddress((void**)&Wqt, g_Wqt);
    cudaGetSymbolAddress((void**)&Wkvt, g_Wkvt);
    cudaGetSymbolAddress((void**)&Wot, g_Wot);

    // operand prep: round x; transpose+round weights to [N][K]
    round4_kernel<<<(MROWS * D_ / 4 + 255) / 256, 256>>>(x, xr, MROWS * D_ / 4);
    transpose_tf32_kernel<<<dim3(D_ / 32, D_ / 32),  dim3(32, 8)>>>(Wq, Wqt, D_, D_);
    transpose_tf32_kernel<<<dim3(KV_ / 32, D_ / 32), dim3(32, 8)>>>(Wk, Wkvt, D_, KV_);
    transpose_tf32_kernel<<<dim3(KV_ / 32, D_ / 32), dim3(32, 8)>>>(Wv, Wkvt + (size_t)KV_ * D_, D_, KV_);
    transpose_tf32_kernel<<<dim3(D_ / 32, D_ / 32),  dim3(32, 8)>>>(Wo, Wot, D_, D_);

    cudaFuncSetAttribute(gemm_tf32_v3, cudaFuncAttributeMaxDynamicSharedMemorySize, GM_SMEM_BYTES);

    // Projections: Q, and fused K|V
    gemm_tf32_v3<<<dim3(D_ / 128, MROWS / 128), 256, GM_SMEM_BYTES>>>(xr, Wqt, Q, D_, D_);
    gemm_tf32_v3<<<dim3(1024 / 128, MROWS / 128), 256, GM_SMEM_BYTES>>>(xr, Wkvt, KV, 1024, D_);

    // RoPE (+ q pre-scale, + k norm, + tf32 rounding of Q/K/V)
    rope_q_kernel<<<MROWS, NH_ * 32>>>();
    rope_k_kernel<<<MROWS, NKV_ * 32>>>();

    // Attention (mma.sync tensor cores)
    flash_mma_kernel<<<dim3(T_ / 64, B_ * NH_), 128>>>();

    // Output projection
    gemm_tf32_v3<<<dim3(D_ / 128, MROWS / 128), 256, GM_SMEM_BYTES>>>(Y, Wot, out, D_, D_);
}

// round 9
// speedup vs baseline: 1.5925x; 1.5925x over previous
#include <cuda_runtime.h>
#include <math.h>
#include <stdint.h>

// Problem constants
#define B_  4
#define T_  1024
#define D_  2048
#define KV_ 512
#define NH_ 32
#define NKV_ 8
#define HD_ 64
#define MROWS (B_*T_)   // 4096

// Scratch (static device globals; no runtime allocation)
__device__ float g_Q[MROWS * D_];      // rope'd, pre-scaled by 1/8, tf32-rounded
__device__ float g_KV[MROWS * 1024];   // per row: [k(512) | v(512)], tf32-rounded
__device__ float g_KN[B_ * NKV_ * T_]; // 0.5*||k||^2 / 8 per key
__device__ float g_Y[MROWS * D_];      // attention out, (b,t,h*hd), tf32-rounded
__device__ float g_xr[MROWS * D_];     // tf32-rounded x
// tf32-rounded weights, natural [K][N] layout
__device__ float g_Wqr[D_ * D_];
__device__ float g_Wkv[D_ * 1024];     // cols 0..511 = Wk, 512..1023 = Wv
__device__ float g_Wor[D_ * D_];

// ---------------------------------------------------------------------------
// helpers
// ---------------------------------------------------------------------------
__device__ __forceinline__ uint32_t f2tf32(float x) {
    uint32_t r;
    asm("cvt.rna.tf32.f32 %0, %1;" : "=r"(r) : "f"(x));
    return r;
}
__device__ __forceinline__ float tf32r(float x) { return __uint_as_float(f2tf32(x)); }

__device__ __forceinline__ void mma_tf32(float c[4],
    uint32_t a0, uint32_t a1, uint32_t a2, uint32_t a3,
    uint32_t b0, uint32_t b1)
{
    asm volatile(
        "mma.sync.aligned.m16n8k8.row.col.f32.tf32.tf32.f32 "
        "{%0,%1,%2,%3}, {%4,%5,%6,%7}, {%8,%9}, {%0,%1,%2,%3};"
        : "+f"(c[0]), "+f"(c[1]), "+f"(c[2]), "+f"(c[3])
        : "r"(a0), "r"(a1), "r"(a2), "r"(a3), "r"(b0), "r"(b1));
}

__device__ __forceinline__ void cp_async16(uint32_t smem, const void* gmem) {
    asm volatile("cp.async.cg.shared.global [%0], [%1], 16;" :: "r"(smem), "l"(gmem));
}
__device__ __forceinline__ void cp_commit() {
    asm volatile("cp.async.commit_group;");
}
template<int N> __device__ __forceinline__ void cp_wait() {
    asm volatile("cp.async.wait_group %0;" :: "n"(N));
}
__device__ __forceinline__ uint32_t smem_u32(const void* p) {
    return (uint32_t)__cvta_generic_to_shared(p);
}

// ---------------------------------------------------------------------------
// tf32 GEMM v4: C[M,N] = A[M,K] @ B[K,N], row-major, pre-rounded tf32.
// 512 threads = 16 warps (4M x 4N), warp tile 32x32, CTA tile 128x128, BK=32.
// 2-stage cp.async. smem: As[2][128][36], Bs[2][32][136].
// A-frag banks (4g+t) bijective; B-frag banks (8t+g) bijective.
// ~85 regs/thread -> no spills under the 512-thread 128-reg budget.
// ---------------------------------------------------------------------------
#define GM_AS_STRIDE 36
#define GM_BS_STRIDE 136
#define GM_AS_ELEMS (2 * 128 * GM_AS_STRIDE)   // 9216 floats
#define GM_BS_ELEMS (2 * 32 * GM_BS_STRIDE)    // 8704 floats
#define GM_SMEM_BYTES ((GM_AS_ELEMS + GM_BS_ELEMS) * 4)  // 71680

__global__ __launch_bounds__(512) void gemm_tf32_v4(
    const float* __restrict__ A, const float* __restrict__ Bm,
    float* __restrict__ C, int N, int K)
{
    extern __shared__ float sm[];
    float* As = sm;                 // [2][128][36]
    float* Bs = sm + GM_AS_ELEMS;   // [2][32][136]

    const int tid  = threadIdx.x;
    const int lane = tid & 31;
    const int wid  = tid >> 5;       // 0..15
    const int g    = lane >> 2;
    const int t    = lane & 3;
    const int wm   = (wid & 3) * 32;   // warp M base
    const int wn   = (wid >> 2) * 32;  // warp N base
    const int bx = blockIdx.x, by = blockIdx.y;

    float acc[2][4][4];
#pragma unroll
    for (int mi = 0; mi < 2; mi++)
#pragma unroll
        for (int nj = 0; nj < 4; nj++)
#pragma unroll
            for (int e = 0; e < 4; e++) acc[mi][nj][e] = 0.f;

    const float* Ab = A  + (size_t)(by * 128) * K;
    const float* Bb = Bm + (size_t)bx * 128;

    // global->smem: A tile 128x32 (8 floats/thr), B tile 32x128 (8 floats/thr)
    const int ar = tid >> 2, ac = (tid & 3) * 8;
    const int br = tid >> 4, bc = (tid & 15) * 8;

    const int niter = K >> 5;

#define AS_IDX(s, r, c) ((((s) * 128) + (r)) * GM_AS_STRIDE + (c))
#define BS_IDX(s, k, c) ((((s) * 32) + (k)) * GM_BS_STRIDE + (c))

    // prologue: tile 0 -> stage 0
    cp_async16(smem_u32(&As[AS_IDX(0, ar, ac)]),     Ab + (size_t)ar * K + ac);
    cp_async16(smem_u32(&As[AS_IDX(0, ar, ac + 4)]), Ab + (size_t)ar * K + ac + 4);
    cp_async16(smem_u32(&Bs[BS_IDX(0, br, bc)]),     Bb + (size_t)br * N + bc);
    cp_async16(smem_u32(&Bs[BS_IDX(0, br, bc + 4)]), Bb + (size_t)br * N + bc + 4);
    cp_commit();

    for (int it = 0; it < niter; it++) {
        const int cb = it & 1;
        if (it + 1 < niter) {
            const int k0 = (it + 1) << 5;
            const int nb = cb ^ 1;
            cp_async16(smem_u32(&As[AS_IDX(nb, ar, ac)]),     Ab + (size_t)ar * K + k0 + ac);
            cp_async16(smem_u32(&As[AS_IDX(nb, ar, ac + 4)]), Ab + (size_t)ar * K + k0 + ac + 4);
            cp_async16(smem_u32(&Bs[BS_IDX(nb, br, bc)]),     Bb + (size_t)(k0 + br) * N + bc);
            cp_async16(smem_u32(&Bs[BS_IDX(nb, br, bc + 4)]), Bb + (size_t)(k0 + br) * N + bc + 4);
            cp_commit();
            cp_wait<1>();
        } else {
            cp_wait<0>();
        }
        __syncthreads();

#pragma unroll
        for (int ks = 0; ks < 4; ks++) {
            const int kc = ks * 8;
            uint32_t a[2][4];
#pragma unroll
            for (int mi = 0; mi < 2; mi++) {
                const int r0 = wm + mi * 16 + g;
                a[mi][0] = __float_as_uint(As[AS_IDX(cb, r0,     kc + t)]);
                a[mi][1] = __float_as_uint(As[AS_IDX(cb, r0 + 8, kc + t)]);
                a[mi][2] = __float_as_uint(As[AS_IDX(cb, r0,     kc + t + 4)]);
                a[mi][3] = __float_as_uint(As[AS_IDX(cb, r0 + 8, kc + t + 4)]);
            }
            uint32_t b[4][2];
#pragma unroll
            for (int nj = 0; nj < 4; nj++) {
                const int c0 = wn + nj * 8 + g;
                b[nj][0] = __float_as_uint(Bs[BS_IDX(cb, kc + t,     c0)]);
                b[nj][1] = __float_as_uint(Bs[BS_IDX(cb, kc + t + 4, c0)]);
            }
#pragma unroll
            for (int mi = 0; mi < 2; mi++)
#pragma unroll
                for (int nj = 0; nj < 4; nj++)
                    mma_tf32(acc[mi][nj], a[mi][0], a[mi][1], a[mi][2], a[mi][3],
                             b[nj][0], b[nj][1]);
        }
        __syncthreads();
    }

#pragma unroll
    for (int mi = 0; mi < 2; mi++) {
        const int r0 = by * 128 + wm + mi * 16 + g;
#pragma unroll
        for (int nj = 0; nj < 4; nj++) {
            const int col = bx * 128 + wn + nj * 8 + 2 * t;
            *(float2*)(C + (size_t)r0 * N + col)       = make_float2(acc[mi][nj][0], acc[mi][nj][1]);
            *(float2*)(C + (size_t)(r0 + 8) * N + col) = make_float2(acc[mi][nj][2], acc[mi][nj][3]);
        }
    }
}

// ---------------------------------------------------------------------------
// Elementwise tf32 rounding pass (float4 per thread)
// ---------------------------------------------------------------------------
__global__ void round4_kernel(const float* __restrict__ s, float* __restrict__ d, int n4)
{
    int i = blockIdx.x * blockDim.x + threadIdx.x;
    if (i < n4) {
        float4 v = ((const float4*)s)[i];
        v.x = tf32r(v.x); v.y = tf32r(v.y); v.z = tf32r(v.z); v.w = tf32r(v.w);
        ((float4*)d)[i] = v;
    }
}

// ---------------------------------------------------------------------------
// Fuse Wk|Wv ([2048][512] each) into [2048][1024], tf32-rounded. float4/thr.
// ---------------------------------------------------------------------------
__global__ void fuse_wkv_kernel(const float* __restrict__ Wk, const float* __restrict__ Wv,
                                float* __restrict__ out)
{
    int i = blockIdx.x * blockDim.x + threadIdx.x;   // float4 index into out
    if (i >= D_ * 256) return;                       // 2048 rows x 256 float4
    int row = i >> 8, p = i & 255;
    const float* src = (p < 128) ? (Wk + (size_t)row * KV_ + p * 4)
                                 : (Wv + (size_t)row * KV_ + (p - 128) * 4);
    float4 v = *(const float4*)src;
    v.x = tf32r(v.x); v.y = tf32r(v.y); v.z = tf32r(v.z); v.w = tf32r(v.w);
    ((float4*)out)[i] = v;
}

// ---------------------------------------------------------------------------
// RoPE for Q (in place): scale by 0.125, round to tf32.
// grid = MROWS, block = NH*32 = 1024.
// ---------------------------------------------------------------------------
__global__ void rope_q_kernel()
{
    const int row  = blockIdx.x;
    const int tpos = row & (T_ - 1);
    const int h = threadIdx.x >> 5;
    const int i = threadIdx.x & 31;

    float inv = 1.0f / powf(10000.0f, (float)i * (1.0f / 32.0f));
    float s, c;
    sincosf((float)tpos * inv, &s, &c);

    float* p = g_Q + (size_t)row * D_ + h * HD_;
    float x1 = p[i], x2 = p[i + 32];
    p[i]      = tf32r((x1 * c - x2 * s) * 0.125f);
    p[i + 32] = tf32r((x2 * c + x1 * s) * 0.125f);
}

// ---------------------------------------------------------------------------
// RoPE for K (in place in g_KV, rounded) + kn from ROUNDED k + round V half.
// grid = MROWS, block = 256 (8 warps: one per kv head).
// ---------------------------------------------------------------------------
__global__ void rope_k_kernel()
{
    const int row  = blockIdx.x;
    const int tpos = row & (T_ - 1);
    const int h = threadIdx.x >> 5;
    const int i = threadIdx.x & 31;

    float inv = 1.0f / powf(10000.0f, (float)i * (1.0f / 32.0f));
    float s, c;
    sincosf((float)tpos * inv, &s, &c);

    float* p = g_KV + (size_t)row * 1024 + h * HD_;
    float x1 = p[i], x2 = p[i + 32];
    float o1 = tf32r(x1 * c - x2 * s);
    float o2 = tf32r(x2 * c + x1 * s);
    p[i]      = o1;
    p[i + 32] = o2;

    float nsq = o1 * o1 + o2 * o2;
#pragma unroll
    for (int off = 16; off; off >>= 1)
        nsq += __shfl_xor_sync(0xffffffffu, nsq, off);
    if (i == 0) {
        int bb = row / T_;
        g_KN[(bb * NKV_ + h) * T_ + tpos] = nsq * 0.0625f;  // 0.5/8
    }

    // round V half (512 floats at offset 512, 256 threads -> 2 each)
    float* vp = g_KV + (size_t)row * 1024 + 512;
    int j = threadIdx.x;
    vp[j]       = tf32r(vp[j]);
    vp[j + 256] = tf32r(vp[j + 256]);
}

// ---------------------------------------------------------------------------
// Flash attention via tf32 mma.sync. Block = 128 thr (4 warps), 64 q-rows.
// grid = (T/64, B*NH); heavy (long causal window) blocks first.
// K/V read from fused g_KV (row stride 1024, V at +512).
// ---------------------------------------------------------------------------
__global__ __launch_bounds__(128) void flash_mma_kernel()
{
    __shared__ float Ks[64][68];
    __shared__ float Vs[64][72];
    __shared__ float kns[64];

    const int bh  = blockIdx.y;
    const int bb  = bh >> 5;
    const int h   = bh & 31;
    const int kvh = h >> 2;
    const int qb  = gridDim.x - 1 - blockIdx.x;   // heavy first
    const int q0  = qb << 6;
    const int tid = threadIdx.x;
    const int w   = tid >> 5;
    const int lane = tid & 31;
    const int g   = lane >> 2;
    const int t   = lane & 3;

    {
        const int r = tid >> 1, ch = (tid & 1) << 5;
        const float* qp = g_Q + (size_t)(bb * T_ + q0 + r) * D_ + h * HD_ + ch;
#pragma unroll
        for (int u = 0; u < 8; u++)
            *(float4*)&Ks[r][ch + 4 * u] = ((const float4*)qp)[u];
    }
    __syncthreads();

    uint32_t aq[8][4];
    const int qr = w * 16 + g;
#pragma unroll
    for (int ks = 0; ks < 8; ks++) {
        aq[ks][0] = __float_as_uint(Ks[qr][ks * 8 + t]);
        aq[ks][1] = __float_as_uint(Ks[qr + 8][ks * 8 + t]);
        aq[ks][2] = __float_as_uint(Ks[qr][ks * 8 + t + 4]);
        aq[ks][3] = __float_as_uint(Ks[qr + 8][ks * 8 + t + 4]);
    }
    __syncthreads();

    float oa[8][4];
#pragma unroll
    for (int nd = 0; nd < 8; nd++)
#pragma unroll
        for (int e = 0; e < 4; e++) oa[nd][e] = 0.f;
    float m0 = -1e30f, m1 = -1e30f, l0 = 0.f, l1 = 0.f;

    const int ntiles = qb + 1;
    const int lr = tid >> 1, lch = (tid & 1) << 5;

    for (int kt = 0; kt < ntiles; kt++) {
        const int kbase = kt << 6;
        const float* kp = g_KV + (size_t)(bb * T_ + kbase + lr) * 1024 + kvh * HD_ + lch;
        const float* vp = kp + 512;

        __syncthreads();
#pragma unroll
        for (int u = 0; u < 8; u++)
            *(float4*)&Ks[lr][lch + 4 * u] = ((const float4*)kp)[u];
#pragma unroll
        for (int u = 0; u < 8; u++)
            *(float4*)&Vs[lr][lch + 4 * u] = ((const float4*)vp)[u];
        if (tid < 64)
            kns[tid] = g_KN[(bb * NKV_ + kvh) * T_ + kbase + tid];
        __syncthreads();

        float sc[8][4];
#pragma unroll
        for (int nj = 0; nj < 8; nj++)
#pragma unroll
            for (int e = 0; e < 4; e++) sc[nj][e] = 0.f;
#pragma unroll
        for (int ks = 0; ks < 8; ks++) {
#pragma unroll
            for (int nj = 0; nj < 8; nj++) {
                uint32_t b0 = __float_as_uint(Ks[nj * 8 + g][ks * 8 + t]);
                uint32_t b1 = __float_as_uint(Ks[nj * 8 + g][ks * 8 + t + 4]);
                mma_tf32(sc[nj], aq[ks][0], aq[ks][1], aq[ks][2], aq[ks][3], b0, b1);
            }
        }

        float mr0 = -1e30f, mr1 = -1e30f;
        const bool diag = (kt == qb);
#pragma unroll
        for (int nj = 0; nj < 8; nj++) {
            const int c0 = nj * 8 + 2 * t, c1 = c0 + 1;
            float kn0 = kns[c0], kn1 = kns[c1];
            sc[nj][0] -= kn0; sc[nj][1] -= kn1;
            sc[nj][2] -= kn0; sc[nj][3] -= kn1;
            if (diag) {
                const int r0 = w * 16 + g, r1 = r0 + 8;
                if (c0 > r0) sc[nj][0] = -1e30f;
                if (c1 > r0) sc[nj][1] = -1e30f;
                if (c0 > r1) sc[nj][2] = -1e30f;
                if (c1 > r1) sc[nj][3] = -1e30f;
            }
            mr0 = fmaxf(mr0, fmaxf(sc[nj][0], sc[nj][1]));
            mr1 = fmaxf(mr1, fmaxf(sc[nj][2], sc[nj][3]));
        }
        mr0 = fmaxf(mr0, __shfl_xor_sync(0xffffffffu, mr0, 1));
        mr0 = fmaxf(mr0, __shfl_xor_sync(0xffffffffu, mr0, 2));
        mr1 = fmaxf(mr1, __shfl_xor_sync(0xffffffffu, mr1, 1));
        mr1 = fmaxf(mr1, __shfl_xor_sync(0xffffffffu, mr1, 2));

        const float mn0 = fmaxf(m0, mr0), mn1 = fmaxf(m1, mr1);
        const float cor0 = __expf(m0 - mn0), cor1 = __expf(m1 - mn1);
        m0 = mn0; m1 = mn1;

        float ps0 = 0.f, ps1 = 0.f;
#pragma unroll
        for (int nj = 0; nj < 8; nj++) {
            sc[nj][0] = __expf(sc[nj][0] - mn0);
            sc[nj][1] = __expf(sc[nj][1] - mn0);
            sc[nj][2] = __expf(sc[nj][2] - mn1);
            sc[nj][3] = __expf(sc[nj][3] - mn1);
            ps0 += sc[nj][0] + sc[nj][1];
            ps1 += sc[nj][2] + sc[nj][3];
        }
        ps0 += __shfl_xor_sync(0xffffffffu, ps0, 1);
        ps0 += __shfl_xor_sync(0xffffffffu, ps0, 2);
        ps1 += __shfl_xor_sync(0xffffffffu, ps1, 1);
        ps1 += __shfl_xor_sync(0xffffffffu, ps1, 2);
        l0 = l0 * cor0 + ps0;
        l1 = l1 * cor1 + ps1;

#pragma unroll
        for (int nd = 0; nd < 8; nd++) {
            oa[nd][0] *= cor0; oa[nd][1] *= cor0;
            oa[nd][2] *= cor1; oa[nd][3] *= cor1;
        }

        const int s0 = (lane & ~3) | (t >> 1);
        const int s1 = s0 + 2;
        const bool odd = (t & 1);
#pragma unroll
        for (int ks = 0; ks < 8; ks++) {
            float p0 = sc[ks][0], p1 = sc[ks][1], p2 = sc[ks][2], p3 = sc[ks][3];
            float x0 = __shfl_sync(0xffffffffu, p0, s0);
            float x1 = __shfl_sync(0xffffffffu, p1, s0);
            float y0 = __shfl_sync(0xffffffffu, p0, s1);
            float y1 = __shfl_sync(0xffffffffu, p1, s1);
            float z0 = __shfl_sync(0xffffffffu, p2, s0);
            float z1 = __shfl_sync(0xffffffffu, p3, s0);
            float u0 = __shfl_sync(0xffffffffu, p2, s1);
            float u1 = __shfl_sync(0xffffffffu, p3, s1);
            uint32_t a0 = f2tf32(odd ? x1 : x0);
            uint32_t a1 = f2tf32(odd ? z1 : z0);
            uint32_t a2 = f2tf32(odd ? y1 : y0);
            uint32_t a3 = f2tf32(odd ? u1 : u0);
#pragma unroll
            for (int nd = 0; nd < 8; nd++) {
                uint32_t b0 = __float_as_uint(Vs[ks * 8 + t][nd * 8 + g]);
                uint32_t b1 = __float_as_uint(Vs[ks * 8 + t + 4][nd * 8 + g]);
                mma_tf32(oa[nd], a0, a1, a2, a3, b0, b1);
            }
        }
    }

    const float il0 = 1.0f / l0, il1 = 1.0f / l1;
    const int qrow = q0 + w * 16 + g;
    float* yp0 = g_Y + (size_t)(bb * T_ + qrow) * D_ + h * HD_;
    float* yp1 = yp0 + (size_t)8 * D_;
#pragma unroll
    for (int nd = 0; nd < 8; nd++) {
        const int col = nd * 8 + 2 * t;
        *(float2*)(yp0 + col) = make_float2(tf32r(oa[nd][0] * il0), tf32r(oa[nd][1] * il0));
        *(float2*)(yp1 + col) = make_float2(tf32r(oa[nd][2] * il1), tf32r(oa[nd][3] * il1));
    }
}

// ---------------------------------------------------------------------------
extern "C" void kernel_launch(void* const* d_in, const int* in_sizes, int n_in,
                              void* d_out, int out_size)
{
    const float* x  = (const float*)d_in[0];
    const float* Wq = (const float*)d_in[1];
    const float* Wk = (const float*)d_in[2];
    const float* Wv = (const float*)d_in[3];
    const float* Wo = (const float*)d_in[4];
    float* out = (float*)d_out;

    float *Q, *KV, *Y, *xr, *Wqr, *Wkv, *Wor;
    cudaGetSymbolAddress((void**)&Q, g_Q);
    cudaGetSymbolAddress((void**)&KV, g_KV);
    cudaGetSymbolAddress((void**)&Y, g_Y);
    cudaGetSymbolAddress((void**)&xr, g_xr);
    cudaGetSymbolAddress((void**)&Wqr, g_Wqr);
    cudaGetSymbolAddress((void**)&Wkv, g_Wkv);
    cudaGetSymbolAddress((void**)&Wor, g_Wor);

    // operand prep: tf32 rounding (natural layouts), fuse Wk|Wv columns
    round4_kernel<<<(MROWS * D_ / 4 + 255) / 256, 256>>>(x, xr, MROWS * D_ / 4);
    round4_kernel<<<(D_ * D_ / 4 + 255) / 256, 256>>>(Wq, Wqr, D_ * D_ / 4);
    fuse_wkv_kernel<<<(D_ * 256 + 255) / 256, 256>>>(Wk, Wv, Wkv);
    round4_kernel<<<(D_ * D_ / 4 + 255) / 256, 256>>>(Wo, Wor, D_ * D_ / 4);

    cudaFuncSetAttribute(gemm_tf32_v4, cudaFuncAttributeMaxDynamicSharedMemorySize, GM_SMEM_BYTES);

    // Projections: Q, and fused K|V
    gemm_tf32_v4<<<dim3(D_ / 128, MROWS / 128), 512, GM_SMEM_BYTES>>>(xr, Wqr, Q, D_, D_);
    gemm_tf32_v4<<<dim3(1024 / 128, MROWS / 128), 512, GM_SMEM_BYTES>>>(xr, Wkv, KV, 1024, D_);

    // RoPE (+ q pre-scale, + k norm, + tf32 rounding of Q/K/V)
    rope_q_kernel<<<MROWS, NH_ * 32>>>();
    rope_k_kernel<<<MROWS, NKV_ * 32>>>();

    // Attention (mma.sync tensor cores)
    flash_mma_kernel<<<dim3(T_ / 64, B_ * NH_), 128>>>();

    // Output projection
    gemm_tf32_v4<<<dim3(D_ / 128, MROWS / 128), 512, GM_SMEM_BYTES>>>(Y, Wor, out, D_, D_);
}

// round 14
// speedup vs baseline: 3.0791x; 1.9335x over previous
#include <cuda_runtime.h>
#include <cuda_fp16.h>
#include <math.h>
#include <stdint.h>

// Problem constants
#define B_  4
#define T_  1024
#define D_  2048
#define KV_ 512
#define NH_ 32
#define NKV_ 8
#define HD_ 64
#define MROWS (B_*T_)   // 4096

// Scratch (static device globals; no runtime allocation)
__device__ float  g_Q[MROWS * D_];      // fp32 Q projection (pre-rope)
__device__ float  g_KV[MROWS * 1024];   // fp32 fused K|V projection (pre-rope)
__device__ float  g_KN[B_ * NKV_ * T_]; // 0.5*||k||^2 / 8 per key (from fp16-rounded k)
__device__ __half g_Qh[MROWS * D_];     // rope'd, scaled 1/8, fp16
__device__ __half g_Kh[MROWS * KV_];    // rope'd K, fp16
__device__ __half g_Vt[B_ * NKV_ * HD_ * T_]; // V transposed per head: [b][kvh][d][t]
__device__ __half g_Yh[MROWS * D_];     // attention out, (b,t,h*hd), fp16
__device__ __half g_xh[MROWS * D_];     // fp16 x
// fp16 TRANSPOSED weights ([N][K] K-major) for GEMM B operand
__device__ __half g_Wqt[D_ * D_];
__device__ __half g_Wkvt[1024 * D_];    // rows 0..511 = Wk^T, 512..1023 = Wv^T
__device__ __half g_Wot[D_ * D_];

// ---------------------------------------------------------------------------
// helpers
// ---------------------------------------------------------------------------
__device__ __forceinline__ uint32_t pack_h2(float a, float b) {
    __half2 h = __floats2half2_rn(a, b);   // low = a, high = b
    return *(uint32_t*)&h;
}

__device__ __forceinline__ void mma_f16(float c[4],
    uint32_t a0, uint32_t a1, uint32_t a2, uint32_t a3,
    uint32_t b0, uint32_t b1)
{
    asm volatile(
        "mma.sync.aligned.m16n8k16.row.col.f32.f16.f16.f32 "
        "{%0,%1,%2,%3}, {%4,%5,%6,%7}, {%8,%9}, {%0,%1,%2,%3};"
        : "+f"(c[0]), "+f"(c[1]), "+f"(c[2]), "+f"(c[3])
        : "r"(a0), "r"(a1), "r"(a2), "r"(a3), "r"(b0), "r"(b1));
}

__device__ __forceinline__ void cp_async16(uint32_t smem, const void* gmem) {
    asm volatile("cp.async.cg.shared.global [%0], [%1], 16;" :: "r"(smem), "l"(gmem));
}
__device__ __forceinline__ void cp_commit() {
    asm volatile("cp.async.commit_group;");
}
template<int N> __device__ __forceinline__ void cp_wait() {
    asm volatile("cp.async.wait_group %0;" :: "n"(N));
}
__device__ __forceinline__ uint32_t smem_u32(const void* p) {
    return (uint32_t)__cvta_generic_to_shared(p);
}

// ---------------------------------------------------------------------------
// fp16 GEMM: C[M,N](f32) = A[M,K](h) @ Bt[N,K](h)^T, both operands K-major.
// Tile 128x128xBK32, 2-stage cp.async, 256 thr (8 warps 2Mx4N), warp 64x32.
// smem (uint = 2 halves along k): As[2][128][20], Bs[2][128][20].
// Tile row = 32 halves = 16 uints: 2 threads/row x 2 cp.async16 each.
// Fragment bank (20*row + kc + t) -> (4g+t) bijective per load.
// ---------------------------------------------------------------------------
#define GH_STRIDE 20                         // uints per row
#define GH_ELEMS (2 * 128 * GH_STRIDE)       // uints per operand (both stages)
#define GH_SMEM_BYTES (2 * GH_ELEMS * 4)     // 40960 bytes

__global__ __launch_bounds__(256) void gemm_f16(
    const __half* __restrict__ A, const __half* __restrict__ Bt,
    float* __restrict__ C, int N, int K)
{
    extern __shared__ uint32_t smu[];
    uint32_t* As = smu;               // [2][128][20]
    uint32_t* Bs = smu + GH_ELEMS;    // [2][128][20]

    const int tid  = threadIdx.x;
    const int lane = tid & 31;
    const int wid  = tid >> 5;
    const int g    = lane >> 2;
    const int t    = lane & 3;
    const int wm   = (wid & 1) * 64;
    const int wn   = (wid >> 1) * 32;
    const int bx = blockIdx.x, by = blockIdx.y;

    float acc[4][4][4];
#pragma unroll
    for (int mi = 0; mi < 4; mi++)
#pragma unroll
        for (int nj = 0; nj < 4; nj++)
#pragma unroll
            for (int e = 0; e < 4; e++) acc[mi][nj][e] = 0.f;

    const __half* Ab = A  + (size_t)(by * 128) * K;
    const __half* Bb = Bt + (size_t)(bx * 128) * K;

    // each tile: 128 rows x 32 halves (16 uints); 2 cp.async16 per thread per operand
    const int r  = tid >> 1;            // 0..127
    const int cu = (tid & 1) * 8;       // uint col base 0 or 8

    const int niter = K >> 5;

#define GH_IDX(s, rr, cc) ((((s) * 128) + (rr)) * GH_STRIDE + (cc))

    // prologue: tile 0 -> stage 0
    cp_async16(smem_u32(&As[GH_IDX(0, r, cu)]),     Ab + (size_t)r * K + cu * 2);
    cp_async16(smem_u32(&As[GH_IDX(0, r, cu + 4)]), Ab + (size_t)r * K + cu * 2 + 8);
    cp_async16(smem_u32(&Bs[GH_IDX(0, r, cu)]),     Bb + (size_t)r * K + cu * 2);
    cp_async16(smem_u32(&Bs[GH_IDX(0, r, cu + 4)]), Bb + (size_t)r * K + cu * 2 + 8);
    cp_commit();

    for (int it = 0; it < niter; it++) {
        const int cb = it & 1;
        if (it + 1 < niter) {
            const int k0 = (it + 1) << 5;   // in halves
            const int nb = cb ^ 1;
            cp_async16(smem_u32(&As[GH_IDX(nb, r, cu)]),     Ab + (size_t)r * K + k0 + cu * 2);
            cp_async16(smem_u32(&As[GH_IDX(nb, r, cu + 4)]), Ab + (size_t)r * K + k0 + cu * 2 + 8);
            cp_async16(smem_u32(&Bs[GH_IDX(nb, r, cu)]),     Bb + (size_t)r * K + k0 + cu * 2);
            cp_async16(smem_u32(&Bs[GH_IDX(nb, r, cu + 4)]), Bb + (size_t)r * K + k0 + cu * 2 + 8);
            cp_commit();
            cp_wait<1>();
        } else {
            cp_wait<0>();
        }
        __syncthreads();

#pragma unroll
        for (int ks = 0; ks < 2; ks++) {      // two k16 chunks per BK32
            const int kc = ks * 8;            // uint offset
            uint32_t a[4][4];
#pragma unroll
            for (int mi = 0; mi < 4; mi++) {
                const int r0 = wm + mi * 16 + g;
                a[mi][0] = As[GH_IDX(cb, r0,     kc + t)];
                a[mi][1] = As[GH_IDX(cb, r0 + 8, kc + t)];
                a[mi][2] = As[GH_IDX(cb, r0,     kc + t + 4)];
                a[mi][3] = As[GH_IDX(cb, r0 + 8, kc + t + 4)];
            }
            uint32_t b[4][2];
#pragma unroll
            for (int nj = 0; nj < 4; nj++) {
                const int n0 = wn + nj * 8 + g;
                b[nj][0] = Bs[GH_IDX(cb, n0, kc + t)];
                b[nj][1] = Bs[GH_IDX(cb, n0, kc + t + 4)];
            }
#pragma unroll
            for (int mi = 0; mi < 4; mi++)
#pragma unroll
                for (int nj = 0; nj < 4; nj++)
                    mma_f16(acc[mi][nj], a[mi][0], a[mi][1], a[mi][2], a[mi][3],
                            b[nj][0], b[nj][1]);
        }
        __syncthreads();
    }

#pragma unroll
    for (int mi = 0; mi < 4; mi++) {
        const int r0 = by * 128 + wm + mi * 16 + g;
#pragma unroll
        for (int nj = 0; nj < 4; nj++) {
            const int col = bx * 128 + wn + nj * 8 + 2 * t;
            *(float2*)(C + (size_t)r0 * N + col)       = make_float2(acc[mi][nj][0], acc[mi][nj][1]);
            *(float2*)(C + (size_t)(r0 + 8) * N + col) = make_float2(acc[mi][nj][2], acc[mi][nj][3]);
        }
    }
}

// ---------------------------------------------------------------------------
// Elementwise f32 -> f16 (half2 per thread)
// ---------------------------------------------------------------------------
__global__ void cvt_half_kernel(const float* __restrict__ s, __half* __restrict__ d, int n2)
{
    int i = blockIdx.x * blockDim.x + threadIdx.x;
    if (i < n2) {
        float2 v = ((const float2*)s)[i];
        ((__half2*)d)[i] = __floats2half2_rn(v.x, v.y);
    }
}

// ---------------------------------------------------------------------------
// Transpose + f16 round: in[rows][cols] f32 -> out[cols][rows] f16
// grid (cols/32, rows/32), block (32,8)
// ---------------------------------------------------------------------------
__global__ void transpose_h_kernel(const float* __restrict__ in, __half* __restrict__ out,
                                   int rows, int cols)
{
    __shared__ float s[32][33];
    const int c0 = blockIdx.x * 32, r0 = blockIdx.y * 32;
    const int tx = threadIdx.x, ty = threadIdx.y;
#pragma unroll
    for (int i = 0; i < 4; i++)
        s[ty + 8 * i][tx] = in[(size_t)(r0 + ty + 8 * i) * cols + c0 + tx];
    __syncthreads();
#pragma unroll
    for (int i = 0; i < 4; i++)
        out[(size_t)(c0 + ty + 8 * i) * rows + r0 + tx] = __float2half_rn(s[tx][ty + 8 * i]);
}

// ---------------------------------------------------------------------------
// RoPE for Q: f32 g_Q -> f16 g_Qh, scaled by 0.125.
// grid = MROWS, block = NH*32 = 1024.
// ---------------------------------------------------------------------------
__global__ void rope_q_kernel()
{
    const int row  = blockIdx.x;
    const int tpos = row & (T_ - 1);
    const int h = threadIdx.x >> 5;
    const int i = threadIdx.x & 31;

    float inv = 1.0f / powf(10000.0f, (float)i * (1.0f / 32.0f));
    float s, c;
    sincosf((float)tpos * inv, &s, &c);

    const float* p = g_Q + (size_t)row * D_ + h * HD_;
    __half* o = g_Qh + (size_t)row * D_ + h * HD_;
    float x1 = p[i], x2 = p[i + 32];
    o[i]      = __float2half_rn((x1 * c - x2 * s) * 0.125f);
    o[i + 32] = __float2half_rn((x2 * c + x1 * s) * 0.125f);
}

// ---------------------------------------------------------------------------
// RoPE for K: f32 g_KV -> f16 g_Kh, kn from f16-rounded k, V -> transposed f16.
// grid = MROWS, block = 256 (8 warps: one per kv head).
// ---------------------------------------------------------------------------
__global__ void rope_k_kernel()
{
    const int row  = blockIdx.x;
    const int tpos = row & (T_ - 1);
    const int h = threadIdx.x >> 5;
    const int i = threadIdx.x & 31;

    float inv = 1.0f / powf(10000.0f, (float)i * (1.0f / 32.0f));
    float s, c;
    sincosf((float)tpos * inv, &s, &c);

    const float* p = g_KV + (size_t)row * 1024 + h * HD_;
    __half* o = g_Kh + (size_t)row * KV_ + h * HD_;
    float x1 = p[i], x2 = p[i + 32];
    __half h1 = __float2half_rn(x1 * c - x2 * s);
    __half h2 = __float2half_rn(x2 * c + x1 * s);
    o[i]      = h1;
    o[i + 32] = h2;

    float o1 = __half2float(h1), o2 = __half2float(h2);
    float nsq = o1 * o1 + o2 * o2;
#pragma unroll
    for (int off = 16; off; off >>= 1)
        nsq += __shfl_xor_sync(0xffffffffu, nsq, off);
    const int bb = row / T_;
    if (i == 0)
        g_KN[(bb * NKV_ + h) * T_ + tpos] = nsq * 0.0625f;  // 0.5/8

    // V: write transposed f16 [b][kvh][d][t]; thread j handles cols j, j+256
    const int j = threadIdx.x;
#pragma unroll
    for (int u = 0; u < 2; u++) {
        int col = j + u * 256;               // 0..511
        int kvh = col >> 6, dd = col & 63;
        float v = g_KV[(size_t)row * 1024 + 512 + col];
        g_Vt[(size_t)((bb * NKV_ + kvh) * HD_ + dd) * T_ + tpos] = __float2half_rn(v);
    }
}

// ---------------------------------------------------------------------------
// Flash attention via fp16 mma (m16n8k16). Block = 128 thr (4 warps), 64 q-rows.
// grid = (T/64, B*NH); heavy (long causal window) blocks first.
// C-fragment of S feeds A-fragment of PV directly (no shuffles).
// smem (uint = 2 halves): Ks[64][36], Vs[64][36]; frag banks (4g+t) bijective.
// ---------------------------------------------------------------------------
__global__ __launch_bounds__(128) void flash_f16_kernel()
{
    __shared__ uint32_t Ks[64 * 36];
    __shared__ uint32_t Vs[64 * 36];
    __shared__ float kns[64];

    const int bh  = blockIdx.y;
    const int bb  = bh >> 5;
    const int h   = bh & 31;
    const int kvh = h >> 2;
    const int qb  = gridDim.x - 1 - blockIdx.x;   // heavy first
    const int q0  = qb << 6;
    const int tid = threadIdx.x;
    const int w   = tid >> 5;
    const int lane = tid & 31;
    const int g   = lane >> 2;
    const int t   = lane & 3;

    const int lr = tid >> 1, lcu = (tid & 1) * 16;   // row, uint-col base for staging

    // ---- stage Q tile (64 q x 32 uints) into Ks, extract A-fragments ----
    {
        const __half* qp = g_Qh + (size_t)(bb * T_ + q0 + lr) * D_ + h * HD_ + lcu * 2;
#pragma unroll
        for (int u = 0; u < 4; u++)
            *(uint4*)&Ks[lr * 36 + lcu + 4 * u] = ((const uint4*)qp)[u];
    }
    __syncthreads();

    uint32_t aq[4][4];
    const int qr = w * 16 + g;
#pragma unroll
    for (int ks = 0; ks < 4; ks++) {
        aq[ks][0] = Ks[qr * 36 + ks * 8 + t];
        aq[ks][1] = Ks[(qr + 8) * 36 + ks * 8 + t];
        aq[ks][2] = Ks[qr * 36 + ks * 8 + t + 4];
        aq[ks][3] = Ks[(qr + 8) * 36 + ks * 8 + t + 4];
    }
    __syncthreads();

    float oa[8][4];
#pragma unroll
    for (int nd = 0; nd < 8; nd++)
#pragma unroll
        for (int e = 0; e < 4; e++) oa[nd][e] = 0.f;
    float m0 = -1e30f, m1 = -1e30f, l0 = 0.f, l1 = 0.f;

    const int ntiles = qb + 1;

    for (int kt = 0; kt < ntiles; kt++) {
        const int kbase = kt << 6;

        __syncthreads();
        {
            const __half* kp = g_Kh + (size_t)(bb * T_ + kbase + lr) * KV_ + kvh * HD_ + lcu * 2;
#pragma unroll
            for (int u = 0; u < 4; u++)
                *(uint4*)&Ks[lr * 36 + lcu + 4 * u] = ((const uint4*)kp)[u];
            const __half* vp = g_Vt + (size_t)((bb * NKV_ + kvh) * HD_ + lr) * T_ + kbase + lcu * 2;
#pragma unroll
            for (int u = 0; u < 4; u++)
                *(uint4*)&Vs[lr * 36 + lcu + 4 * u] = ((const uint4*)vp)[u];
        }
        if (tid < 64)
            kns[tid] = g_KN[(bb * NKV_ + kvh) * T_ + kbase + tid];
        __syncthreads();

        // ---- S = Q K^T : 4 k16 steps x 8 key-blocks ----
        float sc[8][4];
#pragma unroll
        for (int nj = 0; nj < 8; nj++)
#pragma unroll
            for (int e = 0; e < 4; e++) sc[nj][e] = 0.f;
#pragma unroll
        for (int ks = 0; ks < 4; ks++) {
#pragma unroll
            for (int nj = 0; nj < 8; nj++) {
                const int n0 = nj * 8 + g;
                uint32_t b0 = Ks[n0 * 36 + ks * 8 + t];
                uint32_t b1 = Ks[n0 * 36 + ks * 8 + t + 4];
                mma_f16(sc[nj], aq[ks][0], aq[ks][1], aq[ks][2], aq[ks][3], b0, b1);
            }
        }

        // ---- conformal term + causal mask + row maxes ----
        float mr0 = -1e30f, mr1 = -1e30f;
        const bool diag = (kt == qb);
#pragma unroll
        for (int nj = 0; nj < 8; nj++) {
            const int c0 = nj * 8 + 2 * t, c1 = c0 + 1;
            float kn0 = kns[c0], kn1 = kns[c1];
            sc[nj][0] -= kn0; sc[nj][1] -= kn1;
            sc[nj][2] -= kn0; sc[nj][3] -= kn1;
            if (diag) {
                const int r0 = w * 16 + g, r1 = r0 + 8;
                if (c0 > r0) sc[nj][0] = -1e30f;
                if (c1 > r0) sc[nj][1] = -1e30f;
                if (c0 > r1) sc[nj][2] = -1e30f;
                if (c1 > r1) sc[nj][3] = -1e30f;
            }
            mr0 = fmaxf(mr0, fmaxf(sc[nj][0], sc[nj][1]));
            mr1 = fmaxf(mr1, fmaxf(sc[nj][2], sc[nj][3]));
        }
        mr0 = fmaxf(mr0, __shfl_xor_sync(0xffffffffu, mr0, 1));
        mr0 = fmaxf(mr0, __shfl_xor_sync(0xffffffffu, mr0, 2));
        mr1 = fmaxf(mr1, __shfl_xor_sync(0xffffffffu, mr1, 1));
        mr1 = fmaxf(mr1, __shfl_xor_sync(0xffffffffu, mr1, 2));

        const float mn0 = fmaxf(m0, mr0), mn1 = fmaxf(m1, mr1);
        const float cor0 = __expf(m0 - mn0), cor1 = __expf(m1 - mn1);
        m0 = mn0; m1 = mn1;

        // ---- P = exp(S - m), row sums ----
        float ps0 = 0.f, ps1 = 0.f;
#pragma unroll
        for (int nj = 0; nj < 8; nj++) {
            sc[nj][0] = __expf(sc[nj][0] - mn0);
            sc[nj][1] = __expf(sc[nj][1] - mn0);
            sc[nj][2] = __expf(sc[nj][2] - mn1);
            sc[nj][3] = __expf(sc[nj][3] - mn1);
            ps0 += sc[nj][0] + sc[nj][1];
            ps1 += sc[nj][2] + sc[nj][3];
        }
        ps0 += __shfl_xor_sync(0xffffffffu, ps0, 1);
        ps0 += __shfl_xor_sync(0xffffffffu, ps0, 2);
        ps1 += __shfl_xor_sync(0xffffffffu, ps1, 1);
        ps1 += __shfl_xor_sync(0xffffffffu, ps1, 2);
        l0 = l0 * cor0 + ps0;
        l1 = l1 * cor1 + ps1;

        // ---- rescale O ----
#pragma unroll
        for (int nd = 0; nd < 8; nd++) {
            oa[nd][0] *= cor0; oa[nd][1] *= cor0;
            oa[nd][2] *= cor1; oa[nd][3] *= cor1;
        }

        // ---- O += P V : C-frag feeds A-frag directly (no shuffles) ----
#pragma unroll
        for (int j = 0; j < 4; j++) {         // key chunks of 16
            uint32_t a0 = pack_h2(sc[2 * j][0],     sc[2 * j][1]);
            uint32_t a1 = pack_h2(sc[2 * j][2],     sc[2 * j][3]);
            uint32_t a2 = pack_h2(sc[2 * j + 1][0], sc[2 * j + 1][1]);
            uint32_t a3 = pack_h2(sc[2 * j + 1][2], sc[2 * j + 1][3]);
#pragma unroll
            for (int nd = 0; nd < 8; nd++) {
                const int n0 = nd * 8 + g;
                uint32_t b0 = Vs[n0 * 36 + j * 8 + t];
                uint32_t b1 = Vs[n0 * 36 + j * 8 + t + 4];
                mma_f16(oa[nd], a0, a1, a2, a3, b0, b1);
            }
        }
    }

    // ---- normalize + write fp16 Y ----
    const float il0 = 1.0f / l0, il1 = 1.0f / l1;
    const int qrow = q0 + w * 16 + g;
    __half* yp0 = g_Yh + (size_t)(bb * T_ + qrow) * D_ + h * HD_;
    __half* yp1 = yp0 + (size_t)8 * D_;
#pragma unroll
    for (int nd = 0; nd < 8; nd++) {
        const int col = nd * 8 + 2 * t;
        *(__half2*)(yp0 + col) = __floats2half2_rn(oa[nd][0] * il0, oa[nd][1] * il0);
        *(__half2*)(yp1 + col) = __floats2half2_rn(oa[nd][2] * il1, oa[nd][3] * il1);
    }
}

// ---------------------------------------------------------------------------
extern "C" void kernel_launch(void* const* d_in, const int* in_sizes, int n_in,
                              void* d_out, int out_size)
{
    const float* x  = (const float*)d_in[0];
    const float* Wq = (const float*)d_in[1];
    const float* Wk = (const float*)d_in[2];
    const float* Wv = (const float*)d_in[3];
    const float* Wo = (const float*)d_in[4];
    float* out = (float*)d_out;

    float *Q, *KV;
    __half *Qh, *Kh, *Vt, *Yh, *xh, *Wqt, *Wkvt, *Wot;
    cudaGetSymbolAddress((void**)&Q, g_Q);
    cudaGetSymbolAddress((void**)&KV, g_KV);
    cudaGetSymbolAddress((void**)&Qh, g_Qh);
    cudaGetSymbolAddress((void**)&Kh, g_Kh);
    cudaGetSymbolAddress((void**)&Vt, g_Vt);
    cudaGetSymbolAddress((void**)&Yh, g_Yh);
    cudaGetSymbolAddress((void**)&xh, g_xh);
    cudaGetSymbolAddress((void**)&Wqt, g_Wqt);
    cudaGetSymbolAddress((void**)&Wkvt, g_Wkvt);
    cudaGetSymbolAddress((void**)&Wot, g_Wot);

    // operand prep: x -> fp16; weights -> transposed fp16 [N][K]
    cvt_half_kernel<<<(MROWS * D_ / 2 + 255) / 256, 256>>>(x, xh, MROWS * D_ / 2);
    transpose_h_kernel<<<dim3(D_ / 32, D_ / 32),  dim3(32, 8)>>>(Wq, Wqt, D_, D_);
    transpose_h_kernel<<<dim3(KV_ / 32, D_ / 32), dim3(32, 8)>>>(Wk, Wkvt, D_, KV_);
    transpose_h_kernel<<<dim3(KV_ / 32, D_ / 32), dim3(32, 8)>>>(Wv, Wkvt + (size_t)KV_ * D_, D_, KV_);
    transpose_h_kernel<<<dim3(D_ / 32, D_ / 32),  dim3(32, 8)>>>(Wo, Wot, D_, D_);

    // Projections (fp16 tensor cores, f32 accumulate/out)
    gemm_f16<<<dim3(D_ / 128, MROWS / 128), 256, GH_SMEM_BYTES>>>(xh, Wqt, Q, D_, D_);
    gemm_f16<<<dim3(1024 / 128, MROWS / 128), 256, GH_SMEM_BYTES>>>(xh, Wkvt, KV, 1024, D_);

    // RoPE (+ q pre-scale, + k norm, + fp16 conversion, + V transpose)
    rope_q_kernel<<<MROWS, NH_ * 32>>>();
    rope_k_kernel<<<MROWS, NKV_ * 32>>>();

    // Attention (fp16 tensor cores)
    flash_f16_kernel<<<dim3(T_ / 64, B_ * NH_), 128>>>();

    // Output projection
    gemm_f16<<<dim3(D_ / 128, MROWS / 128), 256, GH_SMEM_BYTES>>>(Yh, Wot, out, D_, D_);
}

// round 15
// speedup vs baseline: 3.1705x; 1.0297x over previous
#include <cuda_runtime.h>
#include <cuda_fp16.h>
#include <math.h>
#include <stdint.h>

// Problem constants
#define B_  4
#define T_  1024
#define D_  2048
#define KV_ 512
#define NH_ 32
#define NKV_ 8
#define HD_ 64
#define MROWS (B_*T_)   // 4096

// Scratch (static device globals; no runtime allocation)
__device__ float  g_Q[MROWS * D_];      // fp32 Q projection (pre-rope)
__device__ float  g_KV[MROWS * 1024];   // fp32 fused K|V projection (pre-rope)
__device__ float  g_KN[B_ * NKV_ * T_]; // 0.5*||k||^2 / 8 per key (from fp16-rounded k)
__device__ __half g_Qh[MROWS * D_];     // rope'd, scaled 1/8, fp16
__device__ __half g_Kh[MROWS * KV_];    // rope'd K, fp16
__device__ __half g_Vt[B_ * NKV_ * HD_ * T_]; // V transposed per head: [b][kvh][d][t]
__device__ __half g_Yh[MROWS * D_];     // attention out, (b,t,h*hd), fp16
__device__ __half g_xh[MROWS * D_];     // fp16 x
// fp16 TRANSPOSED weights ([N][K] K-major) for GEMM B operand
__device__ __half g_Wqt[D_ * D_];
__device__ __half g_Wkvt[1024 * D_];    // rows 0..511 = Wk^T, 512..1023 = Wv^T
__device__ __half g_Wot[D_ * D_];

// ---------------------------------------------------------------------------
// helpers
// ---------------------------------------------------------------------------
__device__ __forceinline__ uint32_t pack_h2(float a, float b) {
    __half2 h = __floats2half2_rn(a, b);   // low = a, high = b
    return *(uint32_t*)&h;
}

__device__ __forceinline__ void mma_f16(float c[4],
    uint32_t a0, uint32_t a1, uint32_t a2, uint32_t a3,
    uint32_t b0, uint32_t b1)
{
    asm volatile(
        "mma.sync.aligned.m16n8k16.row.col.f32.f16.f16.f32 "
        "{%0,%1,%2,%3}, {%4,%5,%6,%7}, {%8,%9}, {%0,%1,%2,%3};"
        : "+f"(c[0]), "+f"(c[1]), "+f"(c[2]), "+f"(c[3])
        : "r"(a0), "r"(a1), "r"(a2), "r"(a3), "r"(b0), "r"(b1));
}

__device__ __forceinline__ void cp_async16(uint32_t smem, const void* gmem) {
    asm volatile("cp.async.cg.shared.global [%0], [%1], 16;" :: "r"(smem), "l"(gmem));
}
__device__ __forceinline__ void cp_commit() {
    asm volatile("cp.async.commit_group;");
}
template<int N> __device__ __forceinline__ void cp_wait() {
    asm volatile("cp.async.wait_group %0;" :: "n"(N));
}
__device__ __forceinline__ uint32_t smem_u32(const void* p) {
    return (uint32_t)__cvta_generic_to_shared(p);
}

// ---------------------------------------------------------------------------
// fp16 GEMM: C[M,N](f32) = A[M,K](h) @ Bt[N,K](h)^T, both operands K-major.
// Tile 128x128xBK32, 2-stage cp.async, 256 thr (8 warps 2Mx4N), warp 64x32.
// (unchanged from round 14 — known good at the mma.sync issue ceiling)
// ---------------------------------------------------------------------------
#define GH_STRIDE 20                         // uints per row
#define GH_ELEMS (2 * 128 * GH_STRIDE)       // uints per operand (both stages)
#define GH_SMEM_BYTES (2 * GH_ELEMS * 4)     // 40960 bytes

__global__ __launch_bounds__(256) void gemm_f16(
    const __half* __restrict__ A, const __half* __restrict__ Bt,
    float* __restrict__ C, int N, int K)
{
    extern __shared__ uint32_t smu[];
    uint32_t* As = smu;               // [2][128][20]
    uint32_t* Bs = smu + GH_ELEMS;    // [2][128][20]

    const int tid  = threadIdx.x;
    const int lane = tid & 31;
    const int wid  = tid >> 5;
    const int g    = lane >> 2;
    const int t    = lane & 3;
    const int wm   = (wid & 1) * 64;
    const int wn   = (wid >> 1) * 32;
    const int bx = blockIdx.x, by = blockIdx.y;

    float acc[4][4][4];
#pragma unroll
    for (int mi = 0; mi < 4; mi++)
#pragma unroll
        for (int nj = 0; nj < 4; nj++)
#pragma unroll
            for (int e = 0; e < 4; e++) acc[mi][nj][e] = 0.f;

    const __half* Ab = A  + (size_t)(by * 128) * K;
    const __half* Bb = Bt + (size_t)(bx * 128) * K;

    const int r  = tid >> 1;            // 0..127
    const int cu = (tid & 1) * 8;       // uint col base 0 or 8

    const int niter = K >> 5;

#define GH_IDX(s, rr, cc) ((((s) * 128) + (rr)) * GH_STRIDE + (cc))

    cp_async16(smem_u32(&As[GH_IDX(0, r, cu)]),     Ab + (size_t)r * K + cu * 2);
    cp_async16(smem_u32(&As[GH_IDX(0, r, cu + 4)]), Ab + (size_t)r * K + cu * 2 + 8);
    cp_async16(smem_u32(&Bs[GH_IDX(0, r, cu)]),     Bb + (size_t)r * K + cu * 2);
    cp_async16(smem_u32(&Bs[GH_IDX(0, r, cu + 4)]), Bb + (size_t)r * K + cu * 2 + 8);
    cp_commit();

    for (int it = 0; it < niter; it++) {
        const int cb = it & 1;
        if (it + 1 < niter) {
            const int k0 = (it + 1) << 5;   // in halves
            const int nb = cb ^ 1;
            cp_async16(smem_u32(&As[GH_IDX(nb, r, cu)]),     Ab + (size_t)r * K + k0 + cu * 2);
            cp_async16(smem_u32(&As[GH_IDX(nb, r, cu + 4)]), Ab + (size_t)r * K + k0 + cu * 2 + 8);
            cp_async16(smem_u32(&Bs[GH_IDX(nb, r, cu)]),     Bb + (size_t)r * K + k0 + cu * 2);
            cp_async16(smem_u32(&Bs[GH_IDX(nb, r, cu + 4)]), Bb + (size_t)r * K + k0 + cu * 2 + 8);
            cp_commit();
            cp_wait<1>();
        } else {
            cp_wait<0>();
        }
        __syncthreads();

#pragma unroll
        for (int ks = 0; ks < 2; ks++) {
            const int kc = ks * 8;
            uint32_t a[4][4];
#pragma unroll
            for (int mi = 0; mi < 4; mi++) {
                const int r0 = wm + mi * 16 + g;
                a[mi][0] = As[GH_IDX(cb, r0,     kc + t)];
                a[mi][1] = As[GH_IDX(cb, r0 + 8, kc + t)];
                a[mi][2] = As[GH_IDX(cb, r0,     kc + t + 4)];
                a[mi][3] = As[GH_IDX(cb, r0 + 8, kc + t + 4)];
            }
            uint32_t b[4][2];
#pragma unroll
            for (int nj = 0; nj < 4; nj++) {
                const int n0 = wn + nj * 8 + g;
                b[nj][0] = Bs[GH_IDX(cb, n0, kc + t)];
                b[nj][1] = Bs[GH_IDX(cb, n0, kc + t + 4)];
            }
#pragma unroll
            for (int mi = 0; mi < 4; mi++)
#pragma unroll
                for (int nj = 0; nj < 4; nj++)
                    mma_f16(acc[mi][nj], a[mi][0], a[mi][1], a[mi][2], a[mi][3],
                            b[nj][0], b[nj][1]);
        }
        __syncthreads();
    }

#pragma unroll
    for (int mi = 0; mi < 4; mi++) {
        const int r0 = by * 128 + wm + mi * 16 + g;
#pragma unroll
        for (int nj = 0; nj < 4; nj++) {
            const int col = bx * 128 + wn + nj * 8 + 2 * t;
            *(float2*)(C + (size_t)r0 * N + col)       = make_float2(acc[mi][nj][0], acc[mi][nj][1]);
            *(float2*)(C + (size_t)(r0 + 8) * N + col) = make_float2(acc[mi][nj][2], acc[mi][nj][3]);
        }
    }
}

// ---------------------------------------------------------------------------
// Elementwise f32 -> f16 (half2 per thread)
// ---------------------------------------------------------------------------
__global__ void cvt_half_kernel(const float* __restrict__ s, __half* __restrict__ d, int n2)
{
    int i = blockIdx.x * blockDim.x + threadIdx.x;
    if (i < n2) {
        float2 v = ((const float2*)s)[i];
        ((__half2*)d)[i] = __floats2half2_rn(v.x, v.y);
    }
}

// ---------------------------------------------------------------------------
// Transpose + f16 round: in[rows][cols] f32 -> out[cols][rows] f16
// ---------------------------------------------------------------------------
__global__ void transpose_h_kernel(const float* __restrict__ in, __half* __restrict__ out,
                                   int rows, int cols)
{
    __shared__ float s[32][33];
    const int c0 = blockIdx.x * 32, r0 = blockIdx.y * 32;
    const int tx = threadIdx.x, ty = threadIdx.y;
#pragma unroll
    for (int i = 0; i < 4; i++)
        s[ty + 8 * i][tx] = in[(size_t)(r0 + ty + 8 * i) * cols + c0 + tx];
    __syncthreads();
#pragma unroll
    for (int i = 0; i < 4; i++)
        out[(size_t)(c0 + ty + 8 * i) * rows + r0 + tx] = __float2half_rn(s[tx][ty + 8 * i]);
}

// ---------------------------------------------------------------------------
// Merged Wk/Wv transpose (one launch): z=0 -> Wk^T rows 0..511, z=1 -> Wv^T.
// ---------------------------------------------------------------------------
__global__ void transpose_wkv_kernel(const float* __restrict__ Wk,
                                     const float* __restrict__ Wv,
                                     __half* __restrict__ out)
{
    __shared__ float s[32][33];
    const float* in = blockIdx.z ? Wv : Wk;
    __half* o = out + (size_t)blockIdx.z * KV_ * D_;
    const int c0 = blockIdx.x * 32, r0 = blockIdx.y * 32;
    const int tx = threadIdx.x, ty = threadIdx.y;
#pragma unroll
    for (int i = 0; i < 4; i++)
        s[ty + 8 * i][tx] = in[(size_t)(r0 + ty + 8 * i) * KV_ + c0 + tx];
    __syncthreads();
#pragma unroll
    for (int i = 0; i < 4; i++)
        o[(size_t)(c0 + ty + 8 * i) * D_ + r0 + tx] = __float2half_rn(s[tx][ty + 8 * i]);
}

// ---------------------------------------------------------------------------
// RoPE for Q: f32 g_Q -> f16 g_Qh, scaled by 0.125.
// ---------------------------------------------------------------------------
__global__ void rope_q_kernel()
{
    const int row  = blockIdx.x;
    const int tpos = row & (T_ - 1);
    const int h = threadIdx.x >> 5;
    const int i = threadIdx.x & 31;

    float inv = 1.0f / powf(10000.0f, (float)i * (1.0f / 32.0f));
    float s, c;
    sincosf((float)tpos * inv, &s, &c);

    const float* p = g_Q + (size_t)row * D_ + h * HD_;
    __half* o = g_Qh + (size_t)row * D_ + h * HD_;
    float x1 = p[i], x2 = p[i + 32];
    o[i]      = __float2half_rn((x1 * c - x2 * s) * 0.125f);
    o[i + 32] = __float2half_rn((x2 * c + x1 * s) * 0.125f);
}

// ---------------------------------------------------------------------------
// RoPE for K: f32 g_KV -> f16 g_Kh, kn from f16-rounded k, V -> transposed f16.
// ---------------------------------------------------------------------------
__global__ void rope_k_kernel()
{
    const int row  = blockIdx.x;
    const int tpos = row & (T_ - 1);
    const int h = threadIdx.x >> 5;
    const int i = threadIdx.x & 31;

    float inv = 1.0f / powf(10000.0f, (float)i * (1.0f / 32.0f));
    float s, c;
    sincosf((float)tpos * inv, &s, &c);

    const float* p = g_KV + (size_t)row * 1024 + h * HD_;
    __half* o = g_Kh + (size_t)row * KV_ + h * HD_;
    float x1 = p[i], x2 = p[i + 32];
    __half h1 = __float2half_rn(x1 * c - x2 * s);
    __half h2 = __float2half_rn(x2 * c + x1 * s);
    o[i]      = h1;
    o[i + 32] = h2;

    float o1 = __half2float(h1), o2 = __half2float(h2);
    float nsq = o1 * o1 + o2 * o2;
#pragma unroll
    for (int off = 16; off; off >>= 1)
        nsq += __shfl_xor_sync(0xffffffffu, nsq, off);
    const int bb = row / T_;
    if (i == 0)
        g_KN[(bb * NKV_ + h) * T_ + tpos] = nsq * 0.0625f;  // 0.5/8

    const int j = threadIdx.x;
#pragma unroll
    for (int u = 0; u < 2; u++) {
        int col = j + u * 256;               // 0..511
        int kvh = col >> 6, dd = col & 63;
        float v = g_KV[(size_t)row * 1024 + 512 + col];
        g_Vt[(size_t)((bb * NKV_ + kvh) * HD_ + dd) * T_ + tpos] = __float2half_rn(v);
    }
}

// ---------------------------------------------------------------------------
// Flash attention via fp16 mma, q-tile 128. Block = 256 thr (8 warps).
// grid = (T/128, B*NH); heavy (long causal window) blocks first.
// Per warp: 16 q-rows. K/V tiles of 64 keys staged once for all 8 warps.
// Causal mask generalized via rel = kbase - q0.
// ---------------------------------------------------------------------------
__global__ __launch_bounds__(256) void flash_f16_kernel()
{
    __shared__ uint32_t KVs[2 * 64 * 36];    // Ks = [0..], Vs = [64*36..]
    __shared__ float kns[64];
    uint32_t* Ks = KVs;
    uint32_t* Vs = KVs + 64 * 36;

    const int bh  = blockIdx.y;
    const int bb  = bh >> 5;
    const int h   = bh & 31;
    const int kvh = h >> 2;
    const int qb  = gridDim.x - 1 - blockIdx.x;   // heavy first
    const int q0  = qb << 7;
    const int tid = threadIdx.x;
    const int w   = tid >> 5;
    const int lane = tid & 31;
    const int g   = lane >> 2;
    const int t   = lane & 3;

    // ---- stage Q tile (128 rows x 32 uints) across the whole KVs area ----
    {
        const int lr = tid >> 1, lcu = (tid & 1) * 16;
        const __half* qp = g_Qh + (size_t)(bb * T_ + q0 + lr) * D_ + h * HD_ + lcu * 2;
#pragma unroll
        for (int u = 0; u < 4; u++)
            *(uint4*)&KVs[lr * 36 + lcu + 4 * u] = ((const uint4*)qp)[u];
    }
    __syncthreads();

    uint32_t aq[4][4];
    const int qr = w * 16 + g;               // row in q-tile (0..127)
#pragma unroll
    for (int ks = 0; ks < 4; ks++) {
        aq[ks][0] = KVs[qr * 36 + ks * 8 + t];
        aq[ks][1] = KVs[(qr + 8) * 36 + ks * 8 + t];
        aq[ks][2] = KVs[qr * 36 + ks * 8 + t + 4];
        aq[ks][3] = KVs[(qr + 8) * 36 + ks * 8 + t + 4];
    }
    __syncthreads();

    float oa[8][4];
#pragma unroll
    for (int nd = 0; nd < 8; nd++)
#pragma unroll
        for (int e = 0; e < 4; e++) oa[nd][e] = 0.f;
    float m0 = -1e30f, m1 = -1e30f, l0 = 0.f, l1 = 0.f;

    const int ntiles = (qb << 1) + 2;
    const int lr2 = tid >> 2, lcu2 = (tid & 3) * 8;   // 4 threads per 64-key row

    for (int kt = 0; kt < ntiles; kt++) {
        const int kbase = kt << 6;
        const int rel = kbase - q0;          // >= 0 only for the last two tiles

        __syncthreads();
        {
            const __half* kp = g_Kh + (size_t)(bb * T_ + kbase + lr2) * KV_ + kvh * HD_ + lcu2 * 2;
            *(uint4*)&Ks[lr2 * 36 + lcu2]     = ((const uint4*)kp)[0];
            *(uint4*)&Ks[lr2 * 36 + lcu2 + 4] = ((const uint4*)kp)[1];
            const __half* vp = g_Vt + (size_t)((bb * NKV_ + kvh) * HD_ + lr2) * T_ + kbase + lcu2 * 2;
            *(uint4*)&Vs[lr2 * 36 + lcu2]     = ((const uint4*)vp)[0];
            *(uint4*)&Vs[lr2 * 36 + lcu2 + 4] = ((const uint4*)vp)[1];
        }
        if (tid < 64)
            kns[tid] = g_KN[(bb * NKV_ + kvh) * T_ + kbase + tid];
        __syncthreads();

        // ---- S = Q K^T ----
        float sc[8][4];
#pragma unroll
        for (int nj = 0; nj < 8; nj++)
#pragma unroll
            for (int e = 0; e < 4; e++) sc[nj][e] = 0.f;
#pragma unroll
        for (int ks = 0; ks < 4; ks++) {
#pragma unroll
            for (int nj = 0; nj < 8; nj++) {
                const int n0 = nj * 8 + g;
                uint32_t b0 = Ks[n0 * 36 + ks * 8 + t];
                uint32_t b1 = Ks[n0 * 36 + ks * 8 + t + 4];
                mma_f16(sc[nj], aq[ks][0], aq[ks][1], aq[ks][2], aq[ks][3], b0, b1);
            }
        }

        // ---- conformal term + causal mask + row maxes ----
        float mr0 = -1e30f, mr1 = -1e30f;
        const bool needmask = (rel >= 0);
#pragma unroll
        for (int nj = 0; nj < 8; nj++) {
            const int c0 = nj * 8 + 2 * t, c1 = c0 + 1;
            float kn0 = kns[c0], kn1 = kns[c1];
            sc[nj][0] -= kn0; sc[nj][1] -= kn1;
            sc[nj][2] -= kn0; sc[nj][3] -= kn1;
            if (needmask) {
                const int lim0 = qr - rel, lim1 = lim0 + 8;
                if (c0 > lim0) sc[nj][0] = -1e30f;
                if (c1 > lim0) sc[nj][1] = -1e30f;
                if (c0 > lim1) sc[nj][2] = -1e30f;
                if (c1 > lim1) sc[nj][3] = -1e30f;
            }
            mr0 = fmaxf(mr0, fmaxf(sc[nj][0], sc[nj][1]));
            mr1 = fmaxf(mr1, fmaxf(sc[nj][2], sc[nj][3]));
        }
        mr0 = fmaxf(mr0, __shfl_xor_sync(0xffffffffu, mr0, 1));
        mr0 = fmaxf(mr0, __shfl_xor_sync(0xffffffffu, mr0, 2));
        mr1 = fmaxf(mr1, __shfl_xor_sync(0xffffffffu, mr1, 1));
        mr1 = fmaxf(mr1, __shfl_xor_sync(0xffffffffu, mr1, 2));

        const float mn0 = fmaxf(m0, mr0), mn1 = fmaxf(m1, mr1);
        const float cor0 = __expf(m0 - mn0), cor1 = __expf(m1 - mn1);
        m0 = mn0; m1 = mn1;

        // ---- P = exp(S - m), row sums ----
        float ps0 = 0.f, ps1 = 0.f;
#pragma unroll
        for (int nj = 0; nj < 8; nj++) {
            sc[nj][0] = __expf(sc[nj][0] - mn0);
            sc[nj][1] = __expf(sc[nj][1] - mn0);
            sc[nj][2] = __expf(sc[nj][2] - mn1);
            sc[nj][3] = __expf(sc[nj][3] - mn1);
            ps0 += sc[nj][0] + sc[nj][1];
            ps1 += sc[nj][2] + sc[nj][3];
        }
        ps0 += __shfl_xor_sync(0xffffffffu, ps0, 1);
        ps0 += __shfl_xor_sync(0xffffffffu, ps0, 2);
        ps1 += __shfl_xor_sync(0xffffffffu, ps1, 1);
        ps1 += __shfl_xor_sync(0xffffffffu, ps1, 2);
        l0 = l0 * cor0 + ps0;
        l1 = l1 * cor1 + ps1;

        // ---- rescale O ----
#pragma unroll
        for (int nd = 0; nd < 8; nd++) {
            oa[nd][0] *= cor0; oa[nd][1] *= cor0;
            oa[nd][2] *= cor1; oa[nd][3] *= cor1;
        }

        // ---- O += P V : C-frag feeds A-frag directly ----
#pragma unroll
        for (int j = 0; j < 4; j++) {
            uint32_t a0 = pack_h2(sc[2 * j][0],     sc[2 * j][1]);
            uint32_t a1 = pack_h2(sc[2 * j][2],     sc[2 * j][3]);
            uint32_t a2 = pack_h2(sc[2 * j + 1][0], sc[2 * j + 1][1]);
            uint32_t a3 = pack_h2(sc[2 * j + 1][2], sc[2 * j + 1][3]);
#pragma unroll
            for (int nd = 0; nd < 8; nd++) {
                const int n0 = nd * 8 + g;
                uint32_t b0 = Vs[n0 * 36 + j * 8 + t];
                uint32_t b1 = Vs[n0 * 36 + j * 8 + t + 4];
                mma_f16(oa[nd], a0, a1, a2, a3, b0, b1);
            }
        }
    }

    // ---- normalize + write fp16 Y ----
    const float il0 = 1.0f / l0, il1 = 1.0f / l1;
    const int qrow = q0 + qr;
    __half* yp0 = g_Yh + (size_t)(bb * T_ + qrow) * D_ + h * HD_;
    __half* yp1 = yp0 + (size_t)8 * D_;
#pragma unroll
    for (int nd = 0; nd < 8; nd++) {
        const int col = nd * 8 + 2 * t;
        *(__half2*)(yp0 + col) = __floats2half2_rn(oa[nd][0] * il0, oa[nd][1] * il0);
        *(__half2*)(yp1 + col) = __floats2half2_rn(oa[nd][2] * il1, oa[nd][3] * il1);
    }
}

// ---------------------------------------------------------------------------
extern "C" void kernel_launch(void* const* d_in, const int* in_sizes, int n_in,
                              void* d_out, int out_size)
{
    const float* x  = (const float*)d_in[0];
    const float* Wq = (const float*)d_in[1];
    const float* Wk = (const float*)d_in[2];
    const float* Wv = (const float*)d_in[3];
    const float* Wo = (const float*)d_in[4];
    float* out = (float*)d_out;

    float *Q, *KV;
    __half *Qh, *Kh, *Vt, *Yh, *xh, *Wqt, *Wkvt, *Wot;
    cudaGetSymbolAddress((void**)&Q, g_Q);
    cudaGetSymbolAddress((void**)&KV, g_KV);
    cudaGetSymbolAddress((void**)&Qh, g_Qh);
    cudaGetSymbolAddress((void**)&Kh, g_Kh);
    cudaGetSymbolAddress((void**)&Vt, g_Vt);
    cudaGetSymbolAddress((void**)&Yh, g_Yh);
    cudaGetSymbolAddress((void**)&xh, g_xh);
    cudaGetSymbolAddress((void**)&Wqt, g_Wqt);
    cudaGetSymbolAddress((void**)&Wkvt, g_Wkvt);
    cudaGetSymbolAddress((void**)&Wot, g_Wot);

    // operand prep (4 launches so launch #5 = gemm_f16 for ncu -s 5 -c 1)
    cvt_half_kernel<<<(MROWS * D_ / 2 + 255) / 256, 256>>>(x, xh, MROWS * D_ / 2);
    transpose_h_kernel<<<dim3(D_ / 32, D_ / 32), dim3(32, 8)>>>(Wq, Wqt, D_, D_);
    transpose_wkv_kernel<<<dim3(KV_ / 32, D_ / 32, 2), dim3(32, 8)>>>(Wk, Wv, Wkvt);
    transpose_h_kernel<<<dim3(D_ / 32, D_ / 32), dim3(32, 8)>>>(Wo, Wot, D_, D_);

    // Projections (fp16 tensor cores, f32 accumulate/out)
    gemm_f16<<<dim3(D_ / 128, MROWS / 128), 256, GH_SMEM_BYTES>>>(xh, Wqt, Q, D_, D_);
    gemm_f16<<<dim3(1024 / 128, MROWS / 128), 256, GH_SMEM_BYTES>>>(xh, Wkvt, KV, 1024, D_);

    // RoPE (+ q pre-scale, + k norm, + fp16 conversion, + V transpose)
    rope_q_kernel<<<MROWS, NH_ * 32>>>();
    rope_k_kernel<<<MROWS, NKV_ * 32>>>();

    // Attention (fp16 tensor cores, q-tile 128)
    flash_f16_kernel<<<dim3(T_ / 128, B_ * NH_), 256>>>();

    // Output projection
    gemm_f16<<<dim3(D_ / 128, MROWS / 128), 256, GH_SMEM_BYTES>>>(Yh, Wot, out, D_, D_);
}